// round 16
// baseline (speedup 1.0000x reference)
#include <cuda_runtime.h>

#define BATCH  32
#define NP     4096
#define NSLOT  64                // slot = w*32 + b; opposite cloud = s ^ 32
#define NBX    64
#define NBY    64
#define NB2    (NBX * NBY)
#define XMIN   (-5.0f)
#define W      0.15625f          // 10/64, exact in fp32
#define INVW   6.4f
#define QT     1024              // query-kernel threads (1 query each)

// candidates binned by (x,y), y-minor; preprocessed: (-2x, -2y, -2z, ||c||^2)
__device__ float4         g_pts[NSLOT][NP];
__device__ unsigned short g_qid[NSLOT][NP];
__device__ int            g_bs[NSLOT][NB2 + 1];
__device__ float          g_dist[NSLOT][NP];   // by ORIGINAL index

static __device__ __forceinline__ int bco(float v) {
    int b = (int)floorf((v - XMIN) * INVW);
    return min(max(b, 0), NBX - 1);
}

// ---------------------------------------------------------------------------
// 1) per-slot counting sort by (x,y)-bin. Raw cloud staged once in SMEM.
// ---------------------------------------------------------------------------
__global__ void __launch_bounds__(512)
prep_kernel(const float* __restrict__ x1, const float* __restrict__ x2) {
    extern __shared__ char dyn[];
    float* sp  = (float*)dyn;                    // 3*NP floats (48 KB)
    int* hist  = (int*)(dyn + 3 * NP * sizeof(float));
    int* cur   = hist + NB2;
    __shared__ int wsum[16];

    const int s = blockIdx.x;
    const int w = s >> 5, b = s & 31;
    const float* src = (w ? x2 : x1) + (size_t)b * NP * 3;
    const int tid = threadIdx.x;

    const float4* src4 = (const float4*)src;
    float4* sp4 = (float4*)sp;
    for (int i = tid; i < 3 * NP / 4; i += 512)
        sp4[i] = src4[i];
    for (int i = tid; i < NB2; i += 512) hist[i] = 0;
    __syncthreads();

    for (int i = tid; i < NP; i += 512) {
        int bn = bco(sp[3 * i]) * NBY + bco(sp[3 * i + 1]);
        atomicAdd(&hist[bn], 1);
    }
    __syncthreads();

    const int per = NB2 / 512;
    const int base = tid * per;
    int lsum = 0;
    #pragma unroll
    for (int i = 0; i < per; i++) lsum += hist[base + i];

    int lane = tid & 31, wid = tid >> 5;
    int v = lsum;
    #pragma unroll
    for (int o = 1; o < 32; o <<= 1) {
        int n = __shfl_up_sync(0xffffffffu, v, o);
        if (lane >= o) v += n;
    }
    if (lane == 31) wsum[wid] = v;
    __syncthreads();
    if (wid == 0) {
        int t = (lane < 16) ? wsum[lane] : 0;
        #pragma unroll
        for (int o = 1; o < 16; o <<= 1) {
            int n = __shfl_up_sync(0xffffffffu, t, o);
            if (lane >= o) t += n;
        }
        if (lane < 16) wsum[lane] = t;
    }
    __syncthreads();
    int run = (v - lsum) + (wid > 0 ? wsum[wid - 1] : 0);

    #pragma unroll
    for (int i = 0; i < per; i++) {
        int c = hist[base + i];
        g_bs[s][base + i] = run;
        cur[base + i] = run;
        run += c;
    }
    if (tid == 0) g_bs[s][NB2] = NP;
    __syncthreads();

    for (int i = tid; i < NP; i += 512) {
        float x = sp[3 * i], y = sp[3 * i + 1], z = sp[3 * i + 2];
        int bn = bco(x) * NBY + bco(y);
        int pos = atomicAdd(&cur[bn], 1);
        g_pts[s][pos] = make_float4(-2.0f * x, -2.0f * y, -2.0f * z,
                                    x * x + y * y + z * z);
        g_qid[s][pos] = (unsigned short)i;
    }
}

// scan [S,E) of SMEM-staged candidates with 4 accumulators
#define SCAN_SM(S, E)                                                           \
    {                                                                           \
        int _i = (S), _e = (E);                                                 \
        for (; _i + 4 <= _e; _i += 4) {                                         \
            float4 c0 = scand[_i],     c1 = scand[_i + 1];                      \
            float4 c2 = scand[_i + 2], c3 = scand[_i + 3];                      \
            m0 = fminf(m0, fmaf(qx, c0.x, fmaf(qy, c0.y, fmaf(qz, c0.z, c0.w)))); \
            m1 = fminf(m1, fmaf(qx, c1.x, fmaf(qy, c1.y, fmaf(qz, c1.z, c1.w)))); \
            m2 = fminf(m2, fmaf(qx, c2.x, fmaf(qy, c2.y, fmaf(qz, c2.z, c2.w)))); \
            m3 = fminf(m3, fmaf(qx, c3.x, fmaf(qy, c3.y, fmaf(qz, c3.z, c3.w)))); \
        }                                                                       \
        for (; _i < _e; _i++) {                                                 \
            float4 c0 = scand[_i];                                              \
            m0 = fminf(m0, fmaf(qx, c0.x, fmaf(qy, c0.y, fmaf(qz, c0.z, c0.w)))); \
        }                                                                       \
    }

// ---------------------------------------------------------------------------
// 2) query kernel: 1024 threads = 1024 queries per block (stage amortized 4x).
//    Pass A: warp-uniform (x,y)-rect; fallback: radius-derived rect.
// ---------------------------------------------------------------------------
__global__ void __launch_bounds__(QT)
query_kernel() {
    extern __shared__ float4 scand[];            // NP float4 = 64 KB

    const unsigned FULL = 0xffffffffu;
    const int sq = blockIdx.y;
    const int sc = sq ^ 32;                      // opposite cloud, same batch
    const int tid = threadIdx.x;
    const int qi = blockIdx.x * QT + tid;        // bin-sorted query rank

    const float4* __restrict__ ptsq = g_pts[sq];
    const float4* __restrict__ ptsc = g_pts[sc];
    const int*    __restrict__ bs   = g_bs[sc];

    for (int j = tid; j < NP; j += QT)           // coalesced stage
        scand[j] = ptsc[j];
    __syncthreads();

    float4 qp = ptsq[qi];
    const int qid = g_qid[sq][qi];
    const float qx = -0.5f * qp.x;               // exact inverse of -2x
    const float qy = -0.5f * qp.y;
    const float qz = -0.5f * qp.z;
    const float qq = qp.w;

    const int bx = bco(qx);
    const int by = bco(qy);
    const int XL = max(__reduce_min_sync(FULL, bx) - 1, 0);
    const int XH = min(__reduce_max_sync(FULL, bx) + 1, NBX - 1);
    const int YL = max(__reduce_min_sync(FULL, by) - 1, 0);
    const int YH = min(__reduce_max_sync(FULL, by) + 1, NBY - 1);

    const float INF = __int_as_float(0x7f800000);
    float m0 = INF, m1 = INF, m2 = INF, m3 = INF;

    for (int x = XL; x <= XH; x++)               // one contiguous run per col
        SCAN_SM(bs[x * NBY + YL], bs[x * NBY + YH + 1]);

    float m = fminf(fminf(m0, m1), fminf(m2, m3));
    float ex0 = (XL == 0)       ? INF : qx - (XMIN + (float)XL * W);
    float ex1 = (XH == NBX - 1) ? INF : (XMIN + (float)(XH + 1) * W) - qx;
    float ey0 = (YL == 0)       ? INF : qy - (XMIN + (float)YL * W);
    float ey1 = (YH == NBY - 1) ? INF : (XMIN + (float)(YH + 1) * W) - qy;
    float bnd = fminf(fminf(ex0, ex1), fminf(ey0, ey1));
    float best = qq + m;
    bool fail = !(best <= bnd * bnd * 0.9999f);

    if (__any_sync(FULL, fail)) {
        float d = fail ? sqrtf(best * 1.0002f + 1e-6f) : 0.0f;
        int fxl = fail ? bco(qx - d) : NBX - 1;  // neutral sentinels
        int fxh = fail ? bco(qx + d) : 0;
        int fyl = fail ? bco(qy - d) : NBY - 1;
        int fyh = fail ? bco(qy + d) : 0;
        const int FXL = min(__reduce_min_sync(FULL, fxl), XL);
        const int FXH = max(__reduce_max_sync(FULL, fxh), XH);
        const int FYL = min(__reduce_min_sync(FULL, fyl), YL);
        const int FYH = max(__reduce_max_sync(FULL, fyh), YH);
        for (int x = FXL; x <= FXH; x++) {
            if (x >= XL && x <= XH) {            // overlap cols: only y-fringe
                if (FYL < YL) SCAN_SM(bs[x * NBY + FYL], bs[x * NBY + YL]);
                if (FYH > YH) SCAN_SM(bs[x * NBY + YH + 1], bs[x * NBY + FYH + 1]);
            } else {
                SCAN_SM(bs[x * NBY + FYL], bs[x * NBY + FYH + 1]);
            }
        }
        m = fminf(fminf(m0, m1), fminf(m2, m3));
        best = qq + m;
    }

    g_dist[sq][qid] = best;
}

// ---------------------------------------------------------------------------
// 3) deterministic fixed-order reduce: out[b] = (sum_d0 + sum_d1) / NP
// ---------------------------------------------------------------------------
__global__ void __launch_bounds__(256)
reduce_kernel(float* __restrict__ out) {
    const int b = blockIdx.x, tid = threadIdx.x;
    float s = 0.0f;
    #pragma unroll
    for (int d = 0; d < 2; d++)
        for (int i = tid; i < NP; i += 256)
            s += g_dist[d * BATCH + b][i];

    __shared__ float red[256];
    red[tid] = s;
    __syncthreads();
    #pragma unroll
    for (int o = 128; o > 0; o >>= 1) {
        if (tid < o) red[tid] += red[tid + o];
        __syncthreads();
    }
    if (tid == 0) out[b] = red[0] * (1.0f / (float)NP);
}

extern "C" void kernel_launch(void* const* d_in, const int* in_sizes, int n_in,
                              void* d_out, int out_size) {
    const float* x1 = (const float*)d_in[0];
    const float* x2 = (const float*)d_in[1];
    float* out = (float*)d_out;

    const int prep_smem = 3 * NP * (int)sizeof(float) + 2 * NB2 * (int)sizeof(int);
    cudaFuncSetAttribute(prep_kernel,
                         cudaFuncAttributeMaxDynamicSharedMemorySize, prep_smem);
    cudaFuncSetAttribute(query_kernel,
                         cudaFuncAttributeMaxDynamicSharedMemorySize,
                         NP * (int)sizeof(float4));

    prep_kernel<<<NSLOT, 512, prep_smem>>>(x1, x2);
    query_kernel<<<dim3(NP / QT, NSLOT), QT, NP * sizeof(float4)>>>();
    reduce_kernel<<<BATCH, 256>>>(out);
}